// round 2
// baseline (speedup 1.0000x reference)
#include <cuda_runtime.h>
#include <cstdint>

#define BATCH 4
#define CIN   64
#define COUT  64
#define WDIM  512
#define RES   32
#define TAPS  27

// Conv tiling
#define TCO  32          // couts per block (2 cout tiles)
#define TY   4
#define TZ   4
#define HX   34
#define HXP  36          // padded row
#define HY   6
#define HZ   6
#define CCH  4           // cin chunk
#define NCH  (CIN/CCH)

__device__ float g_styles[BATCH * CIN];
__device__ float g_wmod[BATCH * CIN * TAPS * COUT];   // [b][cin][tap][cout]

using u64 = unsigned long long;

__device__ __forceinline__ u64 fma2(u64 a, u64 b, u64 c) {
    u64 d;
    asm("fma.rn.f32x2 %0, %1, %2, %3;" : "=l"(d) : "l"(a), "l"(b), "l"(c));
    return d;
}
__device__ __forceinline__ u64 pack2(float lo, float hi) {
    u64 r;
    asm("mov.b64 %0, {%1, %2};" : "=l"(r) : "f"(lo), "f"(hi));
    return r;
}
__device__ __forceinline__ void un2(u64 v, float& lo, float& hi) {
    asm("mov.b64 {%0, %1}, %2;" : "=f"(lo), "=f"(hi) : "l"(v));
}

// ---------------------------------------------------------------------------
// Kernel A: styles[b][cin] = w_latent[b] . (affine_w[cin] / sqrt(512)) + affine_b[cin]
// ---------------------------------------------------------------------------
__global__ void k_styles(const float* __restrict__ wl,
                         const float* __restrict__ aw,
                         const float* __restrict__ ab) {
    __shared__ float s_wl[BATCH * WDIM];
    const int tid = threadIdx.x;                 // 256 threads
    for (int i = tid; i < BATCH * WDIM; i += 256) s_wl[i] = wl[i];
    __syncthreads();
    const int b = tid >> 6, c = tid & 63;
    const float* a = aw + c * WDIM;
    const float* w = s_wl + b * WDIM;
    float acc = 0.f;
#pragma unroll 8
    for (int j = 0; j < WDIM; j++) acc += w[j] * a[j];
    g_styles[tid] = acc * 0.044194173824159216f + ab[c];
}

// ---------------------------------------------------------------------------
// Kernel B: modulate + demodulate; store w as [b][cin][tap][cout]
// ---------------------------------------------------------------------------
__global__ void k_wmod(const float* __restrict__ weight) {
    const int b  = blockIdx.x >> 6;
    const int co = blockIdx.x & 63;
    const int tid = threadIdx.x;                 // 256
    __shared__ float s_sty[CIN];
    __shared__ float s_red[8];
    if (tid < CIN) s_sty[tid] = g_styles[b * CIN + tid];
    __syncthreads();
    const float* wr = weight + co * (CIN * TAPS);
    float s = 0.f;
    for (int i = tid; i < CIN * TAPS; i += 256) {
        float v = wr[i] * s_sty[i / TAPS];
        s += v * v;
    }
#pragma unroll
    for (int o = 16; o; o >>= 1) s += __shfl_xor_sync(0xffffffffu, s, o);
    if ((tid & 31) == 0) s_red[tid >> 5] = s;
    __syncthreads();
    if (tid < 32) {
        float t = (tid < 8) ? s_red[tid] : 0.f;
#pragma unroll
        for (int o = 4; o; o >>= 1) t += __shfl_xor_sync(0xffffffffu, t, o);
        if (tid == 0) s_red[0] = t;
    }
    __syncthreads();
    const float d = rsqrtf(s_red[0] + 1e-8f);
    for (int i = tid; i < CIN * TAPS; i += 256) {
        const int cin = i / TAPS;
        const int t   = i - cin * TAPS;
        g_wmod[((b * CIN + cin) * TAPS + t) * COUT + co] = wr[i] * s_sty[cin] * d;
    }
}

// ---------------------------------------------------------------------------
// Kernel C: direct conv3d (per-sample weights), noise add, bias, lrelu * sqrt(2)
// Block: 32 couts x (32 x TY x TZ) voxels. Thread: 8 couts x 8 voxels (f32x2 pairs).
// ---------------------------------------------------------------------------
__global__ void __launch_bounds__(256, 2)
k_conv(const float* __restrict__ x,
       const float* __restrict__ noise,
       const float* __restrict__ bias,
       float* __restrict__ out) {
    __shared__ float  s_in[CCH][HZ][HY][HXP];          // 20736 B
    __shared__ float2 s_w[CCH][TAPS][TCO];             // 27648 B (pre-duplicated pairs)

    const int tid = threadIdx.x;
    const int y0  = blockIdx.x * TY;
    const int z0  = blockIdx.y * TZ;
    const int b   = blockIdx.z >> 1;
    const int ct  = blockIdx.z & 1;

    const int cg  = tid >> 6;           // cout subgroup 0..3
    const int vg  = tid & 63;           // voxel group
    const int vx  = (vg & 3) * 8;
    const int vyL = (vg >> 2) & 3;
    const int vzL = vg >> 4;

    u64 acc[8][4];
#pragma unroll
    for (int j = 0; j < 8; j++)
#pragma unroll
        for (int p = 0; p < 4; p++) acc[j][p] = 0ull;

    for (int ch = 0; ch < NCH; ch++) {
        const int cb = ch * CCH;
        __syncthreads();   // previous chunk fully consumed before overwrite

        // --- stage input halo tile: CCH x 6 x 6 x 34 ---
        for (int i = tid; i < CCH * HZ * HY * HX; i += 256) {
            int c  = i / (HZ * HY * HX);
            int r2 = i - c * (HZ * HY * HX);
            int hz = r2 / (HY * HX);
            int r3 = r2 - hz * (HY * HX);
            int hy = r3 / HX;
            int hx = r3 - hy * HX;
            int gz = z0 - 1 + hz, gy = y0 - 1 + hy, gx = hx - 1;
            float v = 0.f;
            if ((unsigned)gz < RES && (unsigned)gy < RES && (unsigned)gx < RES)
                v = x[((b * CIN + cb + c) * (RES * RES * RES)) + gz * (RES * RES) + gy * RES + gx];
            s_in[c][hz][hy][hx] = v;
        }
        // --- stage weights (duplicated into float2) ---
        for (int i = tid; i < CCH * TAPS * TCO; i += 256) {
            int c  = i / (TAPS * TCO);
            int r2 = i - c * (TAPS * TCO);
            int t  = r2 >> 5;
            int co = r2 & 31;
            float w = g_wmod[((b * CIN + cb + c) * TAPS + t) * COUT + ct * TCO + co];
            s_w[c][t][co] = make_float2(w, w);
        }
        __syncthreads();

        // --- compute ---
#pragma unroll 1
        for (int c = 0; c < CCH; c++) {
#pragma unroll 1
            for (int dz = 0; dz < 3; dz++) {
#pragma unroll
                for (int dy = 0; dy < 3; dy++) {
                    const float* row = &s_in[c][vzL + dz][vyL + dy][vx];
                    u64 p0 = *(const u64*)(row + 0);
                    u64 p1 = *(const u64*)(row + 2);
                    u64 p2 = *(const u64*)(row + 4);
                    u64 p3 = *(const u64*)(row + 6);
                    u64 p4 = *(const u64*)(row + 8);
                    float e0, e1, e2, e3, e4, e5, e6, e7, e8, e9;
                    un2(p0, e0, e1); un2(p1, e2, e3); un2(p2, e4, e5);
                    un2(p3, e6, e7); un2(p4, e8, e9);
                    const u64 q0 = pack2(e1, e2);
                    const u64 q1 = pack2(e3, e4);
                    const u64 q2 = pack2(e5, e6);
                    const u64 q3 = pack2(e7, e8);
#pragma unroll
                    for (int dx = 0; dx < 3; dx++) {
                        u64 i0, i1, i2, i3;
                        if (dx == 0)      { i0 = p0; i1 = p1; i2 = p2; i3 = p3; }
                        else if (dx == 1) { i0 = q0; i1 = q1; i2 = q2; i3 = q3; }
                        else              { i0 = p1; i1 = p2; i2 = p3; i3 = p4; }
                        const u64* wrow = (const u64*)&s_w[c][dz * 9 + dy * 3 + dx][cg * 8];
#pragma unroll
                        for (int j = 0; j < 8; j++) {
                            const u64 w2 = wrow[j];
                            acc[j][0] = fma2(w2, i0, acc[j][0]);
                            acc[j][1] = fma2(w2, i1, acc[j][1]);
                            acc[j][2] = fma2(w2, i2, acc[j][2]);
                            acc[j][3] = fma2(w2, i3, acc[j][3]);
                        }
                    }
                }
            }
        }
    }

    // --- epilogue: + noise + bias, lrelu(0.2) * sqrt(2) ---
    const int vz = z0 + vzL, vy = y0 + vyL;
    const int vbase = vz * (RES * RES) + vy * RES + vx;
    float nz[8];
    const float* np = noise + b * (RES * RES * RES) + vbase;
#pragma unroll
    for (int k = 0; k < 8; k++) nz[k] = np[k];
    const float gain = 1.4142135623730951f;
    const int co0 = ct * TCO + cg * 8;
#pragma unroll
    for (int j = 0; j < 8; j++) {
        const int co = co0 + j;
        const float bb = bias[co];
        float o[8];
#pragma unroll
        for (int p = 0; p < 4; p++) un2(acc[j][p], o[2 * p], o[2 * p + 1]);
        float4 r0, r1;
        float v[8];
#pragma unroll
        for (int k = 0; k < 8; k++) {
            float t = o[k] + nz[k] + bb;
            v[k] = (t > 0.f ? t : 0.2f * t) * gain;
        }
        r0 = make_float4(v[0], v[1], v[2], v[3]);
        r1 = make_float4(v[4], v[5], v[6], v[7]);
        float* op = out + (size_t)(b * COUT + co) * (RES * RES * RES) + vbase;
        *(float4*)(op)     = r0;
        *(float4*)(op + 4) = r1;
    }
}

// ---------------------------------------------------------------------------
extern "C" void kernel_launch(void* const* d_in, const int* in_sizes, int n_in,
                              void* d_out, int out_size) {
    const float* x      = (const float*)d_in[0];
    const float* wl     = (const float*)d_in[1];
    const float* weight = (const float*)d_in[2];
    const float* aw     = (const float*)d_in[3];
    const float* ab     = (const float*)d_in[4];
    const float* noise  = (const float*)d_in[5];
    const float* bias   = (const float*)d_in[6];
    float* out = (float*)d_out;

    k_styles<<<1, 256>>>(wl, aw, ab);
    k_wmod<<<BATCH * COUT, 256>>>(weight);
    dim3 grid(RES / TY, RES / TZ, BATCH * (COUT / TCO));   // (8, 8, 8)
    k_conv<<<grid, 256>>>(x, noise, bias, out);
}

// round 6
// speedup vs baseline: 4.6923x; 4.6923x over previous
#include <cuda_runtime.h>
#include <cstdint>

#define BATCH 4
#define CIN   64
#define COUT  64
#define WDIM  512
#define RES   32
#define VOL   (RES*RES*RES)

// ---------------------------------------------------------------------------
// device globals
// ---------------------------------------------------------------------------
__device__ float g_styles[BATCH * CIN];
// per (b,cin): 8KB = B-matrix [64 cout x 32 taps] tf32, pre-arranged in
// mma.m16n8k8 B-fragment layout: [(ks*8+nt)*32 + lane]*2 + reg
__device__ float g_B[BATCH * CIN * 2048];

__device__ __forceinline__ float f2tf(float f) {
    uint32_t r;
    asm("cvt.rna.tf32.f32 %0, %1;" : "=r"(r) : "f"(f));
    return __uint_as_float(r);
}

__device__ __forceinline__ void mma_tf32(float* c, float a0, float a1, float a2, float a3,
                                         float b0, float b1) {
    asm volatile(
        "mma.sync.aligned.m16n8k8.row.col.f32.tf32.tf32.f32 "
        "{%0,%1,%2,%3}, {%4,%5,%6,%7}, {%8,%9}, {%0,%1,%2,%3};"
        : "+f"(c[0]), "+f"(c[1]), "+f"(c[2]), "+f"(c[3])
        : "r"(__float_as_uint(a0)), "r"(__float_as_uint(a1)),
          "r"(__float_as_uint(a2)), "r"(__float_as_uint(a3)),
          "r"(__float_as_uint(b0)), "r"(__float_as_uint(b1)));
}

// ---------------------------------------------------------------------------
// Kernel A: styles[b][c] = wl[b] . aw[c]/sqrt(512) + ab[c]
// ---------------------------------------------------------------------------
__global__ void k_styles(const float* __restrict__ wl,
                         const float* __restrict__ aw,
                         const float* __restrict__ ab) {
    const int b = blockIdx.x >> 6, c = blockIdx.x & 63;
    const int tid = threadIdx.x;                 // 128
    float acc = 0.f;
    for (int j = tid; j < WDIM; j += 128)
        acc += wl[b * WDIM + j] * aw[c * WDIM + j];
#pragma unroll
    for (int o = 16; o; o >>= 1) acc += __shfl_xor_sync(0xffffffffu, acc, o);
    __shared__ float s[4];
    if ((tid & 31) == 0) s[tid >> 5] = acc;
    __syncthreads();
    if (tid == 0)
        g_styles[blockIdx.x] = (s[0] + s[1] + s[2] + s[3]) * 0.044194173824159216f + ab[c];
}

// ---------------------------------------------------------------------------
// Kernel B: modulate + demodulate -> tf32 B-fragment layout in global
// ---------------------------------------------------------------------------
__global__ void k_wmod(const float* __restrict__ weight) {
    const int b  = blockIdx.x >> 6;
    const int co = blockIdx.x & 63;
    const int tid = threadIdx.x;                 // 256
    __shared__ float s_sty[CIN];
    __shared__ float s_red[8];
    if (tid < CIN) s_sty[tid] = g_styles[b * CIN + tid];
    __syncthreads();
    const float* wr = weight + co * (CIN * 27);
    float s = 0.f;
    for (int i = tid; i < CIN * 27; i += 256) {
        float v = wr[i] * s_sty[i / 27];
        s += v * v;
    }
#pragma unroll
    for (int o = 16; o; o >>= 1) s += __shfl_xor_sync(0xffffffffu, s, o);
    if ((tid & 31) == 0) s_red[tid >> 5] = s;
    __syncthreads();
    if (tid < 32) {
        float t = (tid < 8) ? s_red[tid] : 0.f;
#pragma unroll
        for (int o = 4; o; o >>= 1) t += __shfl_xor_sync(0xffffffffu, t, o);
        if (tid == 0) s_red[0] = t;
    }
    __syncthreads();
    const float d = rsqrtf(s_red[0] + 1e-8f);
    const int nt = co >> 3;
    for (int i = tid; i < CIN * 32; i += 256) {
        const int cin = i >> 5;
        const int t   = i & 31;
        float w = (t < 27) ? wr[cin * 27 + t] * s_sty[cin] * d : 0.f;
        const int ks   = t >> 3;
        const int kk   = t & 7;
        const int reg  = kk >> 2;
        const int lane = ((co & 7) << 2) | (kk & 3);
        const int idx  = (((ks << 3) + nt) * 32 + lane) * 2 + reg;
        g_B[(size_t)(b * CIN + cin) * 2048 + idx] = f2tf(w);
    }
}

// ---------------------------------------------------------------------------
// Kernel C: implicit-GEMM conv via mma.sync tf32 (m16n8k8)
//   CTA: 128 thr / 4 warps; tile: z-plane x 4 y x 32 x (=128 vox) x 64 cout
//   warp w: y-row w, 2 m16 tiles (x 0..15, 16..31), 8 n8 tiles
//   Staging is software-pipelined: global loads for iteration i issue before
//   the barrier that closes iteration i-1's compute.
// ---------------------------------------------------------------------------
__global__ void __launch_bounds__(128, 2)
k_conv(const float* __restrict__ x,
       const float* __restrict__ noise,
       const float* __restrict__ bias,
       float* __restrict__ out) {
    __shared__ float s_halo[3 * 6 * 36];    // [dz][y(6)][x(-1..32, pad 36)]
    __shared__ float s_B[2048];             // B-fragment tile, 8KB

    const int tid = threadIdx.x;
    const int wid = tid >> 5;
    const int lid = tid & 31;
    const int r   = lid >> 2;       // fragment row (x offset)
    const int c   = lid & 3;        // fragment k-low / cout pair selector
    const int z   = blockIdx.x >> 3;
    const int y0  = (blockIdx.x & 7) << 2;
    const int b   = blockIdx.y;
    const int y   = y0 + wid;       // this warp's y row

    // Per-thread halo-staging coordinates (5 elements each, index < 612)
    int hidx[5];     // smem float index, -1 if out of tile
    int gofs[5];     // gmem offset within channel, -1 if padded/zero
#pragma unroll
    for (int k = 0; k < 5; k++) {
        const int i = tid + k * 128;
        if (i < 612) {
            const int hz = i / 204, r2 = i - hz * 204;
            const int hy = r2 / 34,  hx = r2 - hy * 34;
            hidx[k] = hz * 216 + hy * 36 + hx;
            const int gz = z - 1 + hz, gy = y0 - 1 + hy, gx = hx - 1;
            gofs[k] = ((unsigned)gz < RES && (unsigned)gy < RES && (unsigned)gx < RES)
                      ? gz * 1024 + gy * 32 + gx : -1;
        } else { hidx[k] = -1; gofs[k] = -1; }
    }

    // Per-thread tap offsets into halo (float index), -1 = zero (padded tap)
    int offA[4], offB[4];
#pragma unroll
    for (int ks = 0; ks < 4; ks++) {
        const int t0 = ks * 8 + c;
        const int t1 = t0 + 4;
        if (t0 < 27) {
            const int dz = t0 / 9, rm = t0 % 9;
            offA[ks] = dz * 216 + (wid + rm / 3) * 36 + (rm % 3);
        } else offA[ks] = -1;
        if (t1 < 27) {
            const int dz = t1 / 9, rm = t1 % 9;
            offB[ks] = dz * 216 + (wid + rm / 3) * 36 + (rm % 3);
        } else offB[ks] = -1;
    }

    float acc[2][8][4];
#pragma unroll
    for (int mt = 0; mt < 2; mt++)
#pragma unroll
        for (int nt = 0; nt < 8; nt++)
#pragma unroll
            for (int k = 0; k < 4; k++) acc[mt][nt][k] = 0.f;

    const float*  xb = x + (size_t)b * CIN * VOL;
    const float2* Bf = (const float2*)s_B;

#pragma unroll 1
    for (int cin = 0; cin < CIN; cin++) {
        // ---- prefetch (registers only; overlaps previous iter's MMAs) ----
        const float* xc = xb + (size_t)cin * VOL;
        float hv[5];
#pragma unroll
        for (int k = 0; k < 5; k++)
            hv[k] = (gofs[k] >= 0) ? __ldg(xc + gofs[k]) : 0.f;
        const float4* bsrc = (const float4*)(g_B + (size_t)(b * CIN + cin) * 2048);
        float4 bv4[4];
#pragma unroll
        for (int k = 0; k < 4; k++) bv4[k] = __ldg(bsrc + tid + (k << 7));

        __syncthreads();   // previous iteration fully consumed

        // ---- commit to smem ----
#pragma unroll
        for (int k = 0; k < 5; k++)
            if (hidx[k] >= 0) s_halo[hidx[k]] = f2tf(hv[k]);
        {
            float4* dst = (float4*)s_B;
#pragma unroll
            for (int k = 0; k < 4; k++) dst[tid + (k << 7)] = bv4[k];
        }
        __syncthreads();

        // ---- compute: 4 ksteps x 2 mtiles x 8 ntiles ----
#pragma unroll
        for (int ks = 0; ks < 4; ks++) {
            float2 bv[8];
#pragma unroll
            for (int nt = 0; nt < 8; nt++)
                bv[nt] = Bf[((ks << 3) + nt) * 32 + lid];
#pragma unroll
            for (int mt = 0; mt < 2; mt++) {
                const int base = (mt << 4) + r;
                const float a0 = (offA[ks] >= 0) ? s_halo[offA[ks] + base]     : 0.f;
                const float a1 = (offA[ks] >= 0) ? s_halo[offA[ks] + base + 8] : 0.f;
                const float a2 = (offB[ks] >= 0) ? s_halo[offB[ks] + base]     : 0.f;
                const float a3 = (offB[ks] >= 0) ? s_halo[offB[ks] + base + 8] : 0.f;
#pragma unroll
                for (int nt = 0; nt < 8; nt++)
                    mma_tf32(acc[mt][nt], a0, a1, a2, a3, bv[nt].x, bv[nt].y);
            }
        }
    }

    // ---- epilogue: + noise + bias, lrelu(0.2) * sqrt(2) ----
    const float gain = 1.4142135623730951f;
    const int vrow = z * 1024 + y * 32;
    float nzv[2][2];
#pragma unroll
    for (int mt = 0; mt < 2; mt++) {
        nzv[mt][0] = noise[b * VOL + vrow + (mt << 4) + r];
        nzv[mt][1] = noise[b * VOL + vrow + (mt << 4) + r + 8];
    }
    float2 bp[8];
#pragma unroll
    for (int nt = 0; nt < 8; nt++)
        bp[nt] = *(const float2*)(bias + nt * 8 + 2 * c);

#pragma unroll
    for (int nt = 0; nt < 8; nt++) {
        const int co0 = nt * 8 + 2 * c;
        float* o0 = out + ((size_t)(b * COUT + co0) * VOL) + vrow;
#pragma unroll
        for (int mt = 0; mt < 2; mt++) {
            const int xo = (mt << 4) + r;
            float v0 = acc[mt][nt][0] + nzv[mt][0] + bp[nt].x;
            float v1 = acc[mt][nt][1] + nzv[mt][0] + bp[nt].y;
            float v2 = acc[mt][nt][2] + nzv[mt][1] + bp[nt].x;
            float v3 = acc[mt][nt][3] + nzv[mt][1] + bp[nt].y;
            o0[xo]           = (v0 > 0.f ? v0 : 0.2f * v0) * gain;
            o0[VOL + xo]     = (v1 > 0.f ? v1 : 0.2f * v1) * gain;
            o0[xo + 8]       = (v2 > 0.f ? v2 : 0.2f * v2) * gain;
            o0[VOL + xo + 8] = (v3 > 0.f ? v3 : 0.2f * v3) * gain;
        }
    }
}

// ---------------------------------------------------------------------------
extern "C" void kernel_launch(void* const* d_in, const int* in_sizes, int n_in,
                              void* d_out, int out_size) {
    const float* x      = (const float*)d_in[0];
    const float* wl     = (const float*)d_in[1];
    const float* weight = (const float*)d_in[2];
    const float* aw     = (const float*)d_in[3];
    const float* ab     = (const float*)d_in[4];
    const float* noise  = (const float*)d_in[5];
    const float* bias   = (const float*)d_in[6];
    float* out = (float*)d_out;

    k_styles<<<BATCH * CIN, 128>>>(wl, aw, ab);
    k_wmod<<<BATCH * COUT, 256>>>(weight);
    k_conv<<<dim3(256, BATCH), 128>>>(x, noise, bias, out);
}